// round 13
// baseline (speedup 1.0000x reference)
#include <cuda_runtime.h>
#include <cuda_bf16.h>
#include <math.h>
#include <stdint.h>

#define BB 2
#define CC 128
#define HH 96
#define WW 160
#define HWHW (HH*WW)
#define PH98 98
#define PW162 162
#define NPIX (BB*HWHW)
#define COFF 432
#define CIN0P 400
#define KFIN 1152

typedef unsigned long long u64;
typedef __nv_bfloat16 bf16;

// ---------------- device-global scratch ----------------
__device__ __align__(16) bf16 g_ef_hi [BB*PH98*PW162*CIN0P];
__device__ __align__(16) bf16 g_ef_lo [BB*PH98*PW162*CIN0P];
__device__ __align__(16) bf16 g_bA_hi [BB*PH98*PW162*CC];
__device__ __align__(16) bf16 g_bA_lo [BB*PH98*PW162*CC];
__device__ __align__(16) bf16 g_bB_hi [BB*PH98*PW162*CC];
__device__ __align__(16) bf16 g_bB_lo [BB*PH98*PW162*CC];
__device__ float g_h3 [BB*COFF*HWHW];
__device__ __align__(16) bf16 g_val_hi[(long)KFIN*NPIX];   // K-major
__device__ __align__(16) bf16 g_val_lo[(long)KFIN*NPIX];
__device__ __align__(16) bf16 g_w0_hi [9*CC*CIN0P];
__device__ __align__(16) bf16 g_w0_lo [9*CC*CIN0P];
__device__ __align__(16) bf16 g_w1_hi [9*CC*CC];
__device__ __align__(16) bf16 g_w1_lo [9*CC*CC];
__device__ __align__(16) bf16 g_w2_hi [9*CC*CC];
__device__ __align__(16) bf16 g_w2_lo [9*CC*CC];
__device__ __align__(16) bf16 g_w3_hi [9*512*CC];
__device__ __align__(16) bf16 g_w3_lo [9*512*CC];
__device__ __align__(16) bf16 g_wf_hi [CC*KFIN];
__device__ __align__(16) bf16 g_wf_lo [CC*KFIN];

// ---------------- helpers ----------------
__device__ __forceinline__ uint32_t smem_u32(const void* p) {
    uint32_t a;
    asm("{ .reg .u64 t; cvta.to.shared.u64 t, %1; cvt.u32.u64 %0, t; }" : "=r"(a) : "l"(p));
    return a;
}
__device__ __forceinline__ void ldsm4(uint32_t* r, uint32_t a) {
    asm volatile("ldmatrix.sync.aligned.m8n8.x4.shared.b16 {%0,%1,%2,%3}, [%4];"
                 : "=r"(r[0]), "=r"(r[1]), "=r"(r[2]), "=r"(r[3]) : "r"(a));
}
__device__ __forceinline__ void ldsm2(uint32_t* r, uint32_t a) {
    asm volatile("ldmatrix.sync.aligned.m8n8.x2.shared.b16 {%0,%1}, [%2];"
                 : "=r"(r[0]), "=r"(r[1]) : "r"(a));
}
__device__ __forceinline__ void ldsm4t(uint32_t* r, uint32_t a) {
    asm volatile("ldmatrix.sync.aligned.m8n8.x4.trans.shared.b16 {%0,%1,%2,%3}, [%4];"
                 : "=r"(r[0]), "=r"(r[1]), "=r"(r[2]), "=r"(r[3]) : "r"(a));
}
__device__ __forceinline__ void ldsm2t(uint32_t* r, uint32_t a) {
    asm volatile("ldmatrix.sync.aligned.m8n8.x2.trans.shared.b16 {%0,%1}, [%2];"
                 : "=r"(r[0]), "=r"(r[1]) : "r"(a));
}
__device__ __forceinline__ void mma_bf16(float* d, const uint32_t* a, const uint32_t* b) {
    asm volatile("mma.sync.aligned.m16n8k16.row.col.f32.bf16.bf16.f32 "
                 "{%0,%1,%2,%3}, {%4,%5,%6,%7}, {%8,%9}, {%0,%1,%2,%3};"
                 : "+f"(d[0]), "+f"(d[1]), "+f"(d[2]), "+f"(d[3])
                 : "r"(a[0]), "r"(a[1]), "r"(a[2]), "r"(a[3]), "r"(b[0]), "r"(b[1]));
}
__device__ __forceinline__ void split_bf16(float v, bf16& hi, bf16& lo) {
    hi = __float2bfloat16(v);
    lo = __float2bfloat16(v - __bfloat162float(hi));
}
#define CP16(d, s)  asm volatile("cp.async.cg.shared.global [%0], [%1], 16;" :: "r"(d), "l"(s))
#define CPCOMMIT()  asm volatile("cp.async.commit_group;" ::: "memory")
#define CPWAIT0()   asm volatile("cp.async.wait_group 0;" ::: "memory")
#define CPWAIT1()   asm volatile("cp.async.wait_group 1;" ::: "memory")

// ---------------- prep kernels ----------------
__global__ void zero_bufs_k() {
    int i = blockIdx.x * 256 + threadIdx.x;
    if (i >= BB*PH98*PW162*CC) return;
    bf16 z = __float2bfloat16(0.f);
    g_bA_hi[i] = z; g_bA_lo[i] = z; g_bB_hi[i] = z; g_bB_lo[i] = z;
}

__global__ void pack_ef_k(const float* __restrict__ exf, const float* __restrict__ f1,
                          const float* __restrict__ f2) {
    int i = blockIdx.x * 256 + threadIdx.x;
    if (i >= BB*PH98*PW162*CIN0P) return;
    int c  = i % CIN0P;
    int pw = (i / CIN0P) % PW162;
    int ph = (i / (CIN0P*PW162)) % PH98;
    int b  = i / (CIN0P*PW162*PH98);
    float v = 0.f;
    if (ph >= 1 && ph <= HH && pw >= 1 && pw <= WW && c < 388) {
        int p = (ph-1)*WW + (pw-1);
        if (c < 384)      v = exf[(b*384 + c)*HWHW + p];
        else if (c < 386) v = f1[(b*2 + (c-384))*HWHW + p];
        else              v = f2[(b*2 + (c-386))*HWHW + p];
    }
    bf16 hi, lo; split_bf16(v, hi, lo);
    g_ef_hi[i] = hi; g_ef_lo[i] = lo;
}

__global__ void wprep_k(const float* __restrict__ src, bf16* __restrict__ dHi,
                        bf16* __restrict__ dLo, int COUT, int CIN, int CINP, int COUTP) {
    int i = blockIdx.x * 256 + threadIdx.x;
    if (i >= 9*COUTP*CINP) return;
    int ci  = i % CINP;
    int oc  = (i / CINP) % COUTP;
    int tap = i / (CINP*COUTP);
    float v = (oc < COUT && ci < CIN) ? src[((long)oc*CIN + ci)*9 + tap] : 0.f;
    bf16 hi, lo; split_bf16(v, hi, lo);
    dHi[i] = hi; dLo[i] = lo;
}

__global__ void wprep_fin_k(const float* __restrict__ src) {
    int i = blockIdx.x * 256 + threadIdx.x;
    if (i >= CC*KFIN) return;
    int k  = i % KFIN;
    int oc = i / KFIN;
    int ci = k / 9, tap = k % 9;
    float v = src[((long)oc*CC + ci)*9 + tap];
    bf16 hi, lo; split_bf16(v, hi, lo);
    g_wf_hi[i] = hi; g_wf_lo[i] = lo;
}

// ---------------- deform gather (K-major coalesced stores) ----------------
__global__ void gather_k(const float* __restrict__ x, const float* __restrict__ f1,
                         const float* __restrict__ f2) {
    int idx = blockIdx.x * 256 + threadIdx.x;
    if (idx >= BB*16*9*HWHW) return;
    int w = idx % WW;   int t = idx / WW;
    int h = t % HH;     t /= HH;
    int k = t % 9;      t /= 9;
    int dgi = t % 16;
    int b   = t / 16;

    int p = h*WW + w;
    const float* fl = (dgi < 8) ? f1 : f2;
    float fy = fl[(b*2 + 1)*HWHW + p];
    float fx = fl[(b*2 + 0)*HWHW + p];

    int coff = (b*COFF + dgi*18 + k*2)*HWHW + p;
    float dy = 10.f * tanhf(g_h3[coff])        + fy;
    float dx = 10.f * tanhf(g_h3[coff + HWHW]) + fx;
    float mk = 1.f / (1.f + expf(-g_h3[(b*COFF + 288 + dgi*9 + k)*HWHW + p]));

    float py = dy + (float)h + (float)(k/3 - 1);
    float px = dx + (float)w + (float)(k%3 - 1);
    float y0f = floorf(py), x0f = floorf(px);
    float wy = py - y0f, wx = px - x0f;
    int y0 = (int)y0f, x0 = (int)x0f;

    bool vy0 = (y0 >= 0) && (y0 < HH);
    bool vy1 = (y0+1 >= 0) && (y0+1 < HH);
    bool vx0 = (x0 >= 0) && (x0 < WW);
    bool vx1 = (x0+1 >= 0) && (x0+1 < WW);
    int y0c = min(max(y0, 0), HH-1),  y1c = min(max(y0+1, 0), HH-1);
    int x0c = min(max(x0, 0), WW-1),  x1c = min(max(x0+1, 0), WW-1);
    float m00 = (vy0 && vx0) ? (1.f-wy)*(1.f-wx) : 0.f;
    float m01 = (vy0 && vx1) ? (1.f-wy)*wx       : 0.f;
    float m10 = (vy1 && vx0) ? wy*(1.f-wx)       : 0.f;
    float m11 = (vy1 && vx1) ? wy*wx             : 0.f;
    int i00 = y0c*WW + x0c, i01 = y0c*WW + x1c;
    int i10 = y1c*WW + x0c, i11 = y1c*WW + x1c;

    long pix = (long)b*HWHW + p;
    #pragma unroll
    for (int cg = 0; cg < 8; cg++) {
        const float* xp = x + (long)(b*CC + dgi*8 + cg)*HWHW;
        float v = (m00*xp[i00] + m01*xp[i01] + m10*xp[i10] + m11*xp[i11]) * mk;
        bf16 hi, lo; split_bf16(v, hi, lo);
        long di = (long)((dgi*8 + cg)*9 + k)*NPIX + pix;
        g_val_hi[di] = hi; g_val_lo[di] = lo;
    }
}

// ---------------- pipelined mma.sync 3x3 conv kernel ----------------
// CTA: half pixel row (80 px), M=128 oc; 8 warps 4x2; warp tile 32x40.
// bf16 hi/lo 3-term (AhBh + AhBl + AlBh). cp.async double-buffered.
template<int EPI>
__global__ void __launch_bounds__(256, 1)
mma_conv_k(const bf16* __restrict__ wHi, const bf16* __restrict__ wLo,
           const bf16* __restrict__ bHi, const bf16* __restrict__ bLo,
           const float* __restrict__ bias,
           float* __restrict__ outF, bf16* __restrict__ outHi, bf16* __restrict__ outLo,
           int CINP, int MT, int COUT)
{
    constexpr int KC = 16, TAPS = 9;
    constexpr int A_PP    = 128 * KC * 2;                // 4096
    constexpr int A_TAPSZ = 2 * A_PP;
    constexpr int A_REG   = TAPS * A_TAPSZ;              // 73728
    constexpr int BPW     = 82;                          // staged px per ky-row
    constexpr int BROWS   = 3*BPW;                       // 246
    constexpr int B_PLANE = ((BROWS + 7)/8)*128;         // 3968
    constexpr int B_PP    = 2*B_PLANE;                   // 7936
    constexpr int OFF_B   = A_REG;
    constexpr int CHUNK   = A_REG + 2*B_PP;              // 89600
    constexpr int AGRAN   = TAPS * 2 * 128 * (KC/8);     // 4608
    constexpr int BGRAN   = 2 * BROWS * (KC/8);          // 984

    extern __shared__ __align__(128) char sm[];
    const uint32_t sb = smem_u32(sm);

    const int tid  = threadIdx.x;
    const int wid  = tid >> 5;
    const int lane = tid & 31;
    const int wm   = wid & 3;            // 0..3 -> M offset wm*32
    const int wn   = wid >> 2;           // 0..1 -> N offset wn*40
    const int la7  = lane & 7;
    const int hseg = lane >> 4;
    const int pl4  = (lane >> 3) & 1;
    const int rowin4 = la7 + (hseg << 3);

    const int h  = blockIdx.x;
    const int w0 = blockIdx.y * 80;
    const int b  = blockIdx.z / MT;
    const int mt = blockIdx.z % MT;
    const int NCH = CINP / KC;

    float acc[10][4];
    #pragma unroll
    for (int i = 0; i < 10; i++)
        #pragma unroll
        for (int j = 0; j < 4; j++) acc[i][j] = 0.f;

    uint32_t laneA[2];
    #pragma unroll
    for (int mf = 0; mf < 2; mf++) {
        int row = wm*32 + mf*16 + (lane & 15);
        laneA[mf] = hseg*2048 + ((row >> 3) << 7) + ((la7 ^ ((row >> 3) & 7)) << 4);
    }

    auto stage = [&](int buf, int ch) {
        const int cc = ch * KC;
        const uint32_t sbuf = sb + buf*CHUNK;
        #pragma unroll 1
        for (int i = tid; i < AGRAN; i += 256) {
            int m  = i & 127;
            int r  = i >> 7;
            int p  = r & 1;
            int pr = (r >> 1) & 1;
            int t  = r >> 2;
            uint32_t d = sbuf + t*A_TAPSZ + pr*A_PP + p*2048
                + ((m >> 3) << 7) + ((((m & 7)) ^ ((m >> 3) & 7)) << 4);
            const bf16* s = (pr ? wLo : wHi) + ((long)(t*MT + mt)*128 + m)*CINP + cc + p*8;
            CP16(d, s);
        }
        #pragma unroll 1
        for (int i = tid; i < BGRAN; i += 256) {
            int rw = i % BROWS;
            int q  = i / BROWS;
            int p  = q & 1;
            int pr = q >> 1;
            uint32_t d = sbuf + OFF_B + pr*B_PP + p*B_PLANE
                + ((rw >> 3) << 7) + ((((rw & 7)) ^ ((rw >> 3) & 7)) << 4);
            int ky = rw / BPW;
            int pw = rw - ky*BPW;
            const bf16* s = (pr ? bLo : bHi)
                + ((long)((b*PH98 + h + ky)*PW162 + w0 + pw))*CINP + cc + p*8;
            CP16(d, s);
        }
    };

    stage(0, 0);
    CPCOMMIT();

    int buf = 0;
    for (int ch = 0; ch < NCH; ch++) {
        if (ch + 1 < NCH) { stage(buf ^ 1, ch + 1); CPCOMMIT(); CPWAIT1(); }
        else              { CPWAIT0(); }
        __syncthreads();

        const uint32_t sbuf = sb + buf*CHUNK;
        #pragma unroll 1
        for (int tap = 0; tap < TAPS; tap++) {
            const int ky = tap / 3, kx = tap - 3*(tap/3);
            const uint32_t atap = sbuf + tap*A_TAPSZ;
            uint32_t ah[2][4], al[2][4], bh[5][2], bl[5][2];
            #pragma unroll
            for (int mf = 0; mf < 2; mf++) {
                ldsm4(ah[mf], atap + laneA[mf]);
                ldsm4(al[mf], atap + A_PP + laneA[mf]);
            }
            int rb = ky*BPW + wn*40 + kx;
            #pragma unroll
            for (int pr = 0; pr < 2; pr++) {
                uint32_t bbase = sbuf + OFF_B + pr*B_PP + pl4*B_PLANE;
                uint32_t (*bf)[2] = pr ? bl : bh;
                #pragma unroll
                for (int pg = 0; pg < 2; pg++) {
                    int rw = rb + pg*16 + rowin4;
                    uint32_t ad = bbase + ((rw >> 3) << 7)
                                + ((((rw & 7)) ^ ((rw >> 3) & 7)) << 4);
                    ldsm4(&bf[pg*2][0], ad);
                }
                {
                    int rw = rb + 32 + la7;
                    uint32_t ad = bbase + ((rw >> 3) << 7)
                                + ((((rw & 7)) ^ ((rw >> 3) & 7)) << 4);
                    ldsm2(&bf[4][0], ad);
                }
            }
            #pragma unroll
            for (int n = 0; n < 5; n++)
                #pragma unroll
                for (int m = 0; m < 2; m++)
                    mma_bf16(acc[m*5+n], ah[m], bh[n]);
            #pragma unroll
            for (int n = 0; n < 5; n++)
                #pragma unroll
                for (int m = 0; m < 2; m++)
                    mma_bf16(acc[m*5+n], ah[m], bl[n]);
            #pragma unroll
            for (int n = 0; n < 5; n++)
                #pragma unroll
                for (int m = 0; m < 2; m++)
                    mma_bf16(acc[m*5+n], al[m], bh[n]);
        }
        __syncthreads();
        buf ^= 1;
    }

    #pragma unroll
    for (int m = 0; m < 2; m++) {
        #pragma unroll
        for (int half = 0; half < 2; half++) {
            int ml = wm*32 + m*16 + (lane >> 2) + half*8;
            int oc = mt*128 + ml;
            if (oc >= COUT) continue;
            float bz = bias[oc];
            #pragma unroll
            for (int n = 0; n < 5; n++) {
                int nn = wn*40 + n*8 + (lane & 3)*2;
                float v0 = acc[m*5+n][half*2+0] + bz;
                float v1 = acc[m*5+n][half*2+1] + bz;
                if (EPI == 0) {
                    v0 = (v0 >= 0.f) ? v0 : 0.1f*v0;
                    v1 = (v1 >= 0.f) ? v1 : 0.1f*v1;
                    long d0 = ((long)(b*PH98 + h + 1)*PW162 + 1 + w0 + nn)*CC + ml;
                    bf16 h0, l0, h1, l1;
                    split_bf16(v0, h0, l0); split_bf16(v1, h1, l1);
                    outHi[d0] = h0;      outLo[d0] = l0;
                    outHi[d0 + CC] = h1; outLo[d0 + CC] = l1;
                } else {
                    float2 o; o.x = v0; o.y = v1;
                    *(float2*)(outF + ((long)(b*COUT + oc)*HH + h)*WW + w0 + nn) = o;
                }
            }
        }
    }
}

// ---------------- final GEMM: out = Wf * val, K=1152, K-major B ----------
__global__ void __launch_bounds__(256, 1)
mma_gemm_k(const bf16* __restrict__ wHi, const bf16* __restrict__ wLo,
           const bf16* __restrict__ vHi, const bf16* __restrict__ vLo,
           const float* __restrict__ bias, float* __restrict__ outF)
{
    constexpr int KC = 64;
    constexpr int A_PP  = 128 * KC * 2;                  // 16384
    constexpr int A_REG = 2 * A_PP;                      // 32768
    constexpr int BSTR  = 176;                           // 80*2 + 16 pad
    constexpr int B_PP  = KC * BSTR;                     // 11264
    constexpr int OFF_B = A_REG;
    constexpr int CHUNK = A_REG + 2*B_PP;                // 55296
    constexpr int AGRAN = 2 * 128 * (KC/8);              // 2048
    constexpr int BGRAN = 2 * KC * 10;                   // 1280

    extern __shared__ __align__(128) char sm[];
    const uint32_t sb = smem_u32(sm);

    const int tid  = threadIdx.x;
    const int wid  = tid >> 5;
    const int lane = tid & 31;
    const int wm   = wid & 3;
    const int wn   = wid >> 2;
    const int la7  = lane & 7;
    const int hseg = lane >> 4;

    const int h  = blockIdx.x;
    const int w0 = blockIdx.y * 80;
    const int b  = blockIdx.z;
    const long rowpix = (long)b*HWHW + h*WW + w0;   // 80 contiguous pixels
    constexpr int NCH = KFIN / KC;                  // 18

    float acc[10][4];
    #pragma unroll
    for (int i = 0; i < 10; i++)
        #pragma unroll
        for (int j = 0; j < 4; j++) acc[i][j] = 0.f;

    uint32_t laneA[2];
    #pragma unroll
    for (int mf = 0; mf < 2; mf++) {
        int row = wm*32 + mf*16 + (lane & 15);
        laneA[mf] = row * 128;
    }
    const int bg  = lane >> 3;
    const int bk4 = (bg & 1)*8 + la7;
    const int bn4 = (bg >> 1)*8;
    const int bk2 = ((lane >> 3) & 1)*8 + la7;

    auto stage = [&](int buf, int ch) {
        const int cc = ch * KC;
        const uint32_t sbuf = sb + buf*CHUNK;
        #pragma unroll 1
        for (int i = tid; i < AGRAN; i += 256) {
            int g  = i & 7;
            int m  = (i >> 3) & 127;
            int pr = i >> 10;
            uint32_t d = sbuf + pr*A_PP + m*128 + ((g ^ (m & 7)) << 4);
            const bf16* s = (pr ? wLo : wHi) + (long)m*KFIN + cc + g*8;
            CP16(d, s);
        }
        #pragma unroll 1
        for (int i = tid; i < BGRAN; i += 256) {
            int g  = i % 10;
            int t2 = i / 10;
            int pr = (t2 >= KC) ? 1 : 0;
            int rw = t2 - pr*KC;
            uint32_t d = sbuf + OFF_B + pr*B_PP + rw*BSTR + g*16;
            const bf16* s = (pr ? vLo : vHi) + (long)(cc + rw)*NPIX + rowpix + g*8;
            CP16(d, s);
        }
    };

    stage(0, 0);
    CPCOMMIT();

    int buf = 0;
    for (int ch = 0; ch < NCH; ch++) {
        if (ch + 1 < NCH) { stage(buf ^ 1, ch + 1); CPCOMMIT(); CPWAIT1(); }
        else              { CPWAIT0(); }
        __syncthreads();

        const uint32_t sbuf = sb + buf*CHUNK;
        #pragma unroll 1
        for (int ks = 0; ks < KC/16; ks++) {
            uint32_t ah[2][4], al[2][4], bh[5][2], bl[5][2];
            #pragma unroll
            for (int mf = 0; mf < 2; mf++) {
                uint32_t xo = (uint32_t)(((2*ks + hseg) ^ la7) << 4);
                ldsm4(ah[mf], sbuf + laneA[mf] + xo);
                ldsm4(al[mf], sbuf + A_PP + laneA[mf] + xo);
            }
            #pragma unroll
            for (int pr = 0; pr < 2; pr++) {
                uint32_t bbase = sbuf + OFF_B + pr*B_PP + (ks*16)*BSTR;
                uint32_t (*bf)[2] = pr ? bl : bh;
                ldsm4t(&bf[0][0], bbase + bk4*BSTR + (wn*40 + bn4)*2);
                ldsm4t(&bf[2][0], bbase + bk4*BSTR + (wn*40 + 16 + bn4)*2);
                ldsm2t(&bf[4][0], bbase + bk2*BSTR + (wn*40 + 32)*2);
            }
            #pragma unroll
            for (int n = 0; n < 5; n++)
                #pragma unroll
                for (int m = 0; m < 2; m++)
                    mma_bf16(acc[m*5+n], ah[m], bh[n]);
            #pragma unroll
            for (int n = 0; n < 5; n++)
                #pragma unroll
                for (int m = 0; m < 2; m++)
                    mma_bf16(acc[m*5+n], ah[m], bl[n]);
            #pragma unroll
            for (int n = 0; n < 5; n++)
                #pragma unroll
                for (int m = 0; m < 2; m++)
                    mma_bf16(acc[m*5+n], al[m], bh[n]);
        }
        __syncthreads();
        buf ^= 1;
    }

    #pragma unroll
    for (int m = 0; m < 2; m++) {
        #pragma unroll
        for (int half = 0; half < 2; half++) {
            int oc = wm*32 + m*16 + (lane >> 2) + half*8;
            float bz = bias[oc];
            #pragma unroll
            for (int n = 0; n < 5; n++) {
                int nn = wn*40 + n*8 + (lane & 3)*2;
                float2 o;
                o.x = acc[m*5+n][half*2+0] + bz;
                o.y = acc[m*5+n][half*2+1] + bz;
                *(float2*)(outF + ((long)(b*CC + oc)*HH + h)*WW + w0 + nn) = o;
            }
        }
    }
}

// ---------------- launcher ----------------
#define SMEM_HALO (2*(9*2*4096 + 2*7936))       // 179200
#define SMEM_GEMM (2*(2*16384 + 2*11264))       // 110592

extern "C" void kernel_launch(void* const* d_in, const int* in_sizes, int n_in,
                              void* d_out, int out_size)
{
    const float* x    = (const float*)d_in[0];
    const float* exf  = (const float*)d_in[1];
    const float* f1   = (const float*)d_in[2];
    const float* f2   = (const float*)d_in[3];
    const float* wgt  = (const float*)d_in[4];
    const float* bias = (const float*)d_in[5];
    const float* cw0  = (const float*)d_in[6];
    const float* cb0  = (const float*)d_in[7];
    const float* cw1  = (const float*)d_in[8];
    const float* cb1  = (const float*)d_in[9];
    const float* cw2  = (const float*)d_in[10];
    const float* cb2  = (const float*)d_in[11];
    const float* cw3  = (const float*)d_in[12];
    const float* cb3  = (const float*)d_in[13];
    float* out = (float*)d_out;

    cudaFuncSetAttribute(mma_conv_k<0>, cudaFuncAttributeMaxDynamicSharedMemorySize, SMEM_HALO);
    cudaFuncSetAttribute(mma_conv_k<1>, cudaFuncAttributeMaxDynamicSharedMemorySize, SMEM_HALO);
    cudaFuncSetAttribute(mma_gemm_k,    cudaFuncAttributeMaxDynamicSharedMemorySize, SMEM_GEMM);

    void *pefh, *pefl, *pAh, *pAl, *pBh, *pBl, *ph3, *pvh, *pvl;
    void *pw0h, *pw0l, *pw1h, *pw1l, *pw2h, *pw2l, *pw3h, *pw3l, *pwfh, *pwfl;
    cudaGetSymbolAddress(&pefh, g_ef_hi);  cudaGetSymbolAddress(&pefl, g_ef_lo);
    cudaGetSymbolAddress(&pAh, g_bA_hi);   cudaGetSymbolAddress(&pAl, g_bA_lo);
    cudaGetSymbolAddress(&pBh, g_bB_hi);   cudaGetSymbolAddress(&pBl, g_bB_lo);
    cudaGetSymbolAddress(&ph3, g_h3);
    cudaGetSymbolAddress(&pvh, g_val_hi);  cudaGetSymbolAddress(&pvl, g_val_lo);
    cudaGetSymbolAddress(&pw0h, g_w0_hi);  cudaGetSymbolAddress(&pw0l, g_w0_lo);
    cudaGetSymbolAddress(&pw1h, g_w1_hi);  cudaGetSymbolAddress(&pw1l, g_w1_lo);
    cudaGetSymbolAddress(&pw2h, g_w2_hi);  cudaGetSymbolAddress(&pw2l, g_w2_lo);
    cudaGetSymbolAddress(&pw3h, g_w3_hi);  cudaGetSymbolAddress(&pw3l, g_w3_lo);
    cudaGetSymbolAddress(&pwfh, g_wf_hi);  cudaGetSymbolAddress(&pwfl, g_wf_lo);

    zero_bufs_k<<<(BB*PH98*PW162*CC + 255)/256, 256>>>();
    pack_ef_k<<<(BB*PH98*PW162*CIN0P + 255)/256, 256>>>(exf, f1, f2);
    wprep_k<<<(9*CC*CIN0P + 255)/256, 256>>>(cw0, (bf16*)pw0h, (bf16*)pw0l, 128, 388, CIN0P, 128);
    wprep_k<<<(9*CC*CC   + 255)/256, 256>>>(cw1, (bf16*)pw1h, (bf16*)pw1l, 128, 128, 128, 128);
    wprep_k<<<(9*CC*CC   + 255)/256, 256>>>(cw2, (bf16*)pw2h, (bf16*)pw2l, 128, 128, 128, 128);

    dim3 g1(HH, 2, BB);
    mma_conv_k<0><<<g1, 256, SMEM_HALO>>>(
        (const bf16*)pw0h, (const bf16*)pw0l, (const bf16*)pefh, (const bf16*)pefl,
        cb0, nullptr, (bf16*)pAh, (bf16*)pAl, CIN0P, 1, 128);

    wprep_k<<<(9*512*CC  + 255)/256, 256>>>(cw3, (bf16*)pw3h, (bf16*)pw3l, COFF, 128, 128, 512);
    wprep_fin_k<<<(CC*KFIN + 255)/256, 256>>>(wgt);

    mma_conv_k<0><<<g1, 256, SMEM_HALO>>>(
        (const bf16*)pw1h, (const bf16*)pw1l, (const bf16*)pAh, (const bf16*)pAl,
        cb1, nullptr, (bf16*)pBh, (bf16*)pBl, 128, 1, 128);
    mma_conv_k<0><<<g1, 256, SMEM_HALO>>>(
        (const bf16*)pw2h, (const bf16*)pw2l, (const bf16*)pBh, (const bf16*)pBl,
        cb2, nullptr, (bf16*)pAh, (bf16*)pAl, 128, 1, 128);

    dim3 g3(HH, 2, BB*4);
    mma_conv_k<1><<<g3, 256, SMEM_HALO>>>(
        (const bf16*)pw3h, (const bf16*)pw3l, (const bf16*)pAh, (const bf16*)pAl,
        cb3, (float*)ph3, nullptr, nullptr, 128, 4, COFF);

    gather_k<<<(BB*16*9*HWHW + 255)/256, 256>>>(x, f1, f2);

    mma_gemm_k<<<g1, 256, SMEM_GEMM>>>(
        (const bf16*)pwfh, (const bf16*)pwfl, (const bf16*)pvh, (const bf16*)pvl,
        bias, out);
}

// round 17
// speedup vs baseline: 1.1956x; 1.1956x over previous
#include <cuda_runtime.h>
#include <cuda_bf16.h>
#include <math.h>
#include <stdint.h>

#define BB 2
#define CC 128
#define HH 96
#define WW 160
#define HWHW (HH*WW)
#define PH98 98
#define PW162 162
#define NPIX (BB*HWHW)
#define COFF 432
#define CIN0P 400
#define KFIN 1152

typedef unsigned long long u64;
typedef __nv_bfloat16 bf16;

// ---------------- device-global scratch ----------------
__device__ __align__(16) bf16 g_ef_hi [BB*PH98*PW162*CIN0P];
__device__ __align__(16) bf16 g_ef_lo [BB*PH98*PW162*CIN0P];
__device__ __align__(16) bf16 g_bA_hi [BB*PH98*PW162*CC];
__device__ __align__(16) bf16 g_bA_lo [BB*PH98*PW162*CC];
__device__ __align__(16) bf16 g_bB_hi [BB*PH98*PW162*CC];
__device__ __align__(16) bf16 g_bB_lo [BB*PH98*PW162*CC];
__device__ float g_h3 [BB*COFF*HWHW];
__device__ __align__(16) bf16 g_val_hi[(long)KFIN*NPIX];   // K-major
__device__ __align__(16) bf16 g_val_lo[(long)KFIN*NPIX];
__device__ __align__(16) bf16 g_w0_hi [9*CC*CIN0P];
__device__ __align__(16) bf16 g_w0_lo [9*CC*CIN0P];
__device__ __align__(16) bf16 g_w1_hi [9*CC*CC];
__device__ __align__(16) bf16 g_w1_lo [9*CC*CC];
__device__ __align__(16) bf16 g_w2_hi [9*CC*CC];
__device__ __align__(16) bf16 g_w2_lo [9*CC*CC];
__device__ __align__(16) bf16 g_w3_hi [9*512*CC];
__device__ __align__(16) bf16 g_w3_lo [9*512*CC];
__device__ __align__(16) bf16 g_wf_hi [CC*KFIN];
__device__ __align__(16) bf16 g_wf_lo [CC*KFIN];

// ---------------- helpers ----------------
__device__ __forceinline__ uint32_t smem_u32(const void* p) {
    uint32_t a;
    asm("{ .reg .u64 t; cvta.to.shared.u64 t, %1; cvt.u32.u64 %0, t; }" : "=r"(a) : "l"(p));
    return a;
}
__device__ __forceinline__ void ldsm4(uint32_t* r, uint32_t a) {
    asm volatile("ldmatrix.sync.aligned.m8n8.x4.shared.b16 {%0,%1,%2,%3}, [%4];"
                 : "=r"(r[0]), "=r"(r[1]), "=r"(r[2]), "=r"(r[3]) : "r"(a));
}
__device__ __forceinline__ void ldsm2(uint32_t* r, uint32_t a) {
    asm volatile("ldmatrix.sync.aligned.m8n8.x2.shared.b16 {%0,%1}, [%2];"
                 : "=r"(r[0]), "=r"(r[1]) : "r"(a));
}
__device__ __forceinline__ void ldsm4t(uint32_t* r, uint32_t a) {
    asm volatile("ldmatrix.sync.aligned.m8n8.x4.trans.shared.b16 {%0,%1,%2,%3}, [%4];"
                 : "=r"(r[0]), "=r"(r[1]), "=r"(r[2]), "=r"(r[3]) : "r"(a));
}
__device__ __forceinline__ void ldsm2t(uint32_t* r, uint32_t a) {
    asm volatile("ldmatrix.sync.aligned.m8n8.x2.trans.shared.b16 {%0,%1}, [%2];"
                 : "=r"(r[0]), "=r"(r[1]) : "r"(a));
}
__device__ __forceinline__ void mma_bf16(float* d, const uint32_t* a, const uint32_t* b) {
    asm volatile("mma.sync.aligned.m16n8k16.row.col.f32.bf16.bf16.f32 "
                 "{%0,%1,%2,%3}, {%4,%5,%6,%7}, {%8,%9}, {%0,%1,%2,%3};"
                 : "+f"(d[0]), "+f"(d[1]), "+f"(d[2]), "+f"(d[3])
                 : "r"(a[0]), "r"(a[1]), "r"(a[2]), "r"(a[3]), "r"(b[0]), "r"(b[1]));
}
__device__ __forceinline__ void split_bf16(float v, bf16& hi, bf16& lo) {
    hi = __float2bfloat16(v);
    lo = __float2bfloat16(v - __bfloat162float(hi));
}
#define CP16(d, s)  asm volatile("cp.async.cg.shared.global [%0], [%1], 16;" :: "r"(d), "l"(s))
#define CPCOMMIT()  asm volatile("cp.async.commit_group;" ::: "memory")
#define CPWAIT0()   asm volatile("cp.async.wait_group 0;" ::: "memory")
#define CPWAIT1()   asm volatile("cp.async.wait_group 1;" ::: "memory")

// ---------------- prep kernels ----------------
__global__ void zero_bufs_k() {
    int i = blockIdx.x * 256 + threadIdx.x;
    if (i >= BB*PH98*PW162*CC) return;
    bf16 z = __float2bfloat16(0.f);
    g_bA_hi[i] = z; g_bA_lo[i] = z; g_bB_hi[i] = z; g_bB_lo[i] = z;
}

__global__ void pack_ef_k(const float* __restrict__ exf, const float* __restrict__ f1,
                          const float* __restrict__ f2) {
    int i = blockIdx.x * 256 + threadIdx.x;
    if (i >= BB*PH98*PW162*CIN0P) return;
    int c  = i % CIN0P;
    int pw = (i / CIN0P) % PW162;
    int ph = (i / (CIN0P*PW162)) % PH98;
    int b  = i / (CIN0P*PW162*PH98);
    float v = 0.f;
    if (ph >= 1 && ph <= HH && pw >= 1 && pw <= WW && c < 388) {
        int p = (ph-1)*WW + (pw-1);
        if (c < 384)      v = exf[(b*384 + c)*HWHW + p];
        else if (c < 386) v = f1[(b*2 + (c-384))*HWHW + p];
        else              v = f2[(b*2 + (c-386))*HWHW + p];
    }
    bf16 hi, lo; split_bf16(v, hi, lo);
    g_ef_hi[i] = hi; g_ef_lo[i] = lo;
}

__global__ void wprep_k(const float* __restrict__ src, bf16* __restrict__ dHi,
                        bf16* __restrict__ dLo, int COUT, int CIN, int CINP, int COUTP) {
    int i = blockIdx.x * 256 + threadIdx.x;
    if (i >= 9*COUTP*CINP) return;
    int ci  = i % CINP;
    int oc  = (i / CINP) % COUTP;
    int tap = i / (CINP*COUTP);
    float v = (oc < COUT && ci < CIN) ? src[((long)oc*CIN + ci)*9 + tap] : 0.f;
    bf16 hi, lo; split_bf16(v, hi, lo);
    dHi[i] = hi; dLo[i] = lo;
}

__global__ void wprep_fin_k(const float* __restrict__ src) {
    int i = blockIdx.x * 256 + threadIdx.x;
    if (i >= CC*KFIN) return;
    int k  = i % KFIN;
    int oc = i / KFIN;
    int ci = k / 9, tap = k % 9;
    float v = src[((long)oc*CC + ci)*9 + tap];
    bf16 hi, lo; split_bf16(v, hi, lo);
    g_wf_hi[i] = hi; g_wf_lo[i] = lo;
}

// ---------------- deform gather (K-major coalesced stores) ----------------
__global__ void gather_k(const float* __restrict__ x, const float* __restrict__ f1,
                         const float* __restrict__ f2) {
    int idx = blockIdx.x * 256 + threadIdx.x;
    if (idx >= BB*16*9*HWHW) return;
    int w = idx % WW;   int t = idx / WW;
    int h = t % HH;     t /= HH;
    int k = t % 9;      t /= 9;
    int dgi = t % 16;
    int b   = t / 16;

    int p = h*WW + w;
    const float* fl = (dgi < 8) ? f1 : f2;
    float fy = fl[(b*2 + 1)*HWHW + p];
    float fx = fl[(b*2 + 0)*HWHW + p];

    int coff = (b*COFF + dgi*18 + k*2)*HWHW + p;
    float dy = 10.f * tanhf(g_h3[coff])        + fy;
    float dx = 10.f * tanhf(g_h3[coff + HWHW]) + fx;
    float mk = 1.f / (1.f + expf(-g_h3[(b*COFF + 288 + dgi*9 + k)*HWHW + p]));

    float py = dy + (float)h + (float)(k/3 - 1);
    float px = dx + (float)w + (float)(k%3 - 1);
    float y0f = floorf(py), x0f = floorf(px);
    float wy = py - y0f, wx = px - x0f;
    int y0 = (int)y0f, x0 = (int)x0f;

    bool vy0 = (y0 >= 0) && (y0 < HH);
    bool vy1 = (y0+1 >= 0) && (y0+1 < HH);
    bool vx0 = (x0 >= 0) && (x0 < WW);
    bool vx1 = (x0+1 >= 0) && (x0+1 < WW);
    int y0c = min(max(y0, 0), HH-1),  y1c = min(max(y0+1, 0), HH-1);
    int x0c = min(max(x0, 0), WW-1),  x1c = min(max(x0+1, 0), WW-1);
    float m00 = (vy0 && vx0) ? (1.f-wy)*(1.f-wx) : 0.f;
    float m01 = (vy0 && vx1) ? (1.f-wy)*wx       : 0.f;
    float m10 = (vy1 && vx0) ? wy*(1.f-wx)       : 0.f;
    float m11 = (vy1 && vx1) ? wy*wx             : 0.f;
    int i00 = y0c*WW + x0c, i01 = y0c*WW + x1c;
    int i10 = y1c*WW + x0c, i11 = y1c*WW + x1c;

    long pix = (long)b*HWHW + p;
    #pragma unroll
    for (int cg = 0; cg < 8; cg++) {
        const float* xp = x + (long)(b*CC + dgi*8 + cg)*HWHW;
        float v = (m00*xp[i00] + m01*xp[i01] + m10*xp[i10] + m11*xp[i11]) * mk;
        bf16 hi, lo; split_bf16(v, hi, lo);
        long di = (long)((dgi*8 + cg)*9 + k)*NPIX + pix;
        g_val_hi[di] = hi; g_val_lo[di] = lo;
    }
}

// ---------------- per-tap pipelined mma.sync 3x3 conv ----------------
// CTA: (h, 80px half-row, mt). 8 warps 4x2; warp tile 32x40.
// Iteration it = kc*9 + tap. A slot = it%3 (8KB/iter), B slot = kc%3 (15.9KB/kchunk).
// Slots derived FUNCTIONALLY from indices (no mutable slot state).
// Depth-3 rings -> 70.5KB smem -> 2 CTAs/SM. 3-term bf16 hi/lo.
#define A_SLOT 8192
#define B_SLOT 15872
#define OFFB_C (3*A_SLOT)
#define SMEM_CONV (3*A_SLOT + 3*B_SLOT)       // 72192

template<int EPI>
__global__ void __launch_bounds__(256, 2)
mma_conv_k(const bf16* __restrict__ wHi, const bf16* __restrict__ wLo,
           const bf16* __restrict__ bHi, const bf16* __restrict__ bLo,
           const float* __restrict__ bias,
           float* __restrict__ outF, bf16* __restrict__ outHi, bf16* __restrict__ outLo,
           int CINP, int MT, int COUT)
{
    constexpr int BPW = 82, BROWS = 3*BPW;

    extern __shared__ __align__(128) char sm[];
    const uint32_t sb = smem_u32(sm);

    const int tid  = threadIdx.x;
    const int wid  = tid >> 5;
    const int lane = tid & 31;
    const int wm   = wid & 3;
    const int wn   = wid >> 2;
    const int la7  = lane & 7;
    const int hseg = lane >> 4;
    const int pl4  = (lane >> 3) & 1;
    const int rowin4 = la7 + (hseg << 3);

    const int h  = blockIdx.x;
    const int w0 = blockIdx.y * 80;
    const int b  = blockIdx.z / MT;
    const int mt = blockIdx.z % MT;
    const int NCH = CINP >> 4;
    const int NIT = NCH * 9;

    float acc[10][4];
    #pragma unroll
    for (int i = 0; i < 10; i++)
        #pragma unroll
        for (int j = 0; j < 4; j++) acc[i][j] = 0.f;

    uint32_t laneA[2];
    #pragma unroll
    for (int mf = 0; mf < 2; mf++) {
        int row = wm*32 + mf*16 + (lane & 15);
        laneA[mf] = hseg*2048 + ((row >> 3) << 7) + ((la7 ^ ((row >> 3) & 7)) << 4);
    }

    auto stageA = [&](int slot, int kc, int tap) {
        #pragma unroll
        for (int i = tid; i < 512; i += 256) {
            int m  = i & 127;
            int r  = i >> 7;
            int p  = r & 1;
            int pr = r >> 1;
            uint32_t d = sb + slot*A_SLOT + pr*4096 + p*2048
                + ((m >> 3) << 7) + ((((m & 7)) ^ ((m >> 3) & 7)) << 4);
            const bf16* s = (pr ? wLo : wHi)
                + ((long)(tap*MT + mt)*128 + m)*CINP + kc*16 + p*8;
            CP16(d, s);
        }
    };
    auto stageB = [&](int slot, int kc) {
        #pragma unroll 1
        for (int i = tid; i < 2*BROWS*2; i += 256) {
            int rw = i % BROWS;
            int q  = i / BROWS;
            int p  = q & 1;
            int pr = q >> 1;
            uint32_t d = sb + OFFB_C + slot*B_SLOT + pr*7936 + p*3968
                + ((rw >> 3) << 7) + ((((rw & 7)) ^ ((rw >> 3) & 7)) << 4);
            int ky = rw / BPW;
            int pw = rw - ky*BPW;
            const bf16* s = (pr ? bLo : bHi)
                + ((long)((b*PH98 + h + ky)*PW162 + w0 + pw))*CINP + kc*16 + p*8;
            CP16(d, s);
        }
    };

    // prologue: stage iteration 0 (A slot 0, B slot 0)
    stageA(0, 0, 0);
    stageB(0, 0);
    CPCOMMIT();

    for (int it = 0; it < NIT; it++) {
        // prefetch iteration it+1 into functionally-derived slots
        const int itn = it + 1;
        if (itn < NIT) {
            const int kcn = itn / 9, tapn = itn - 9*(itn/9);
            stageA(itn % 3, kcn, tapn);
            if (tapn == 0) stageB(kcn % 3, kcn);
        }
        CPCOMMIT();
        CPWAIT1();
        __syncthreads();

        // compute iteration it from A slot it%3, B slot kc%3
        const int kc  = it / 9;
        const int tap = it - 9*kc;
        const int ky = tap / 3, kx = tap - 3*(tap/3);
        const uint32_t abase = sb + (it % 3)*A_SLOT;
        uint32_t ah[2][4], al[2][4], bh[5][2], bl[5][2];
        #pragma unroll
        for (int mf = 0; mf < 2; mf++) {
            ldsm4(ah[mf], abase + laneA[mf]);
            ldsm4(al[mf], abase + 4096 + laneA[mf]);
        }
        int rb = ky*BPW + wn*40 + kx;
        #pragma unroll
        for (int pr = 0; pr < 2; pr++) {
            uint32_t bbase = sb + OFFB_C + (kc % 3)*B_SLOT + pr*7936 + pl4*3968;
            uint32_t (*bf)[2] = pr ? bl : bh;
            #pragma unroll
            for (int pg = 0; pg < 2; pg++) {
                int rw = rb + pg*16 + rowin4;
                uint32_t ad = bbase + ((rw >> 3) << 7)
                            + ((((rw & 7)) ^ ((rw >> 3) & 7)) << 4);
                ldsm4(&bf[pg*2][0], ad);
            }
            {
                int rw = rb + 32 + la7;
                uint32_t ad = bbase + ((rw >> 3) << 7)
                            + ((((rw & 7)) ^ ((rw >> 3) & 7)) << 4);
                ldsm2(&bf[4][0], ad);
            }
        }
        #pragma unroll
        for (int n = 0; n < 5; n++)
            #pragma unroll
            for (int m = 0; m < 2; m++)
                mma_bf16(acc[m*5+n], ah[m], bh[n]);
        #pragma unroll
        for (int n = 0; n < 5; n++)
            #pragma unroll
            for (int m = 0; m < 2; m++)
                mma_bf16(acc[m*5+n], ah[m], bl[n]);
        #pragma unroll
        for (int n = 0; n < 5; n++)
            #pragma unroll
            for (int m = 0; m < 2; m++)
                mma_bf16(acc[m*5+n], al[m], bh[n]);
    }

    // ---- epilogue ----
    #pragma unroll
    for (int m = 0; m < 2; m++) {
        #pragma unroll
        for (int half = 0; half < 2; half++) {
            int ml = wm*32 + m*16 + (lane >> 2) + half*8;
            int oc = mt*128 + ml;
            if (oc >= COUT) continue;
            float bz = bias[oc];
            #pragma unroll
            for (int n = 0; n < 5; n++) {
                int nn = wn*40 + n*8 + (lane & 3)*2;
                float v0 = acc[m*5+n][half*2+0] + bz;
                float v1 = acc[m*5+n][half*2+1] + bz;
                if (EPI == 0) {
                    v0 = (v0 >= 0.f) ? v0 : 0.1f*v0;
                    v1 = (v1 >= 0.f) ? v1 : 0.1f*v1;
                    long d0 = ((long)(b*PH98 + h + 1)*PW162 + 1 + w0 + nn)*CC + ml;
                    bf16 h0, l0, h1, l1;
                    split_bf16(v0, h0, l0); split_bf16(v1, h1, l1);
                    outHi[d0] = h0;      outLo[d0] = l0;
                    outHi[d0 + CC] = h1; outLo[d0 + CC] = l1;
                } else {
                    float2 o; o.x = v0; o.y = v1;
                    *(float2*)(outF + ((long)(b*COUT + oc)*HH + h)*WW + w0 + nn) = o;
                }
            }
        }
    }
}

// ---------------- final GEMM: out = Wf * val, K=1152, K-major B ----------
__global__ void __launch_bounds__(256, 1)
mma_gemm_k(const bf16* __restrict__ wHi, const bf16* __restrict__ wLo,
           const bf16* __restrict__ vHi, const bf16* __restrict__ vLo,
           const float* __restrict__ bias, float* __restrict__ outF)
{
    constexpr int KC = 64;
    constexpr int A_PP  = 128 * KC * 2;
    constexpr int A_REG = 2 * A_PP;
    constexpr int BSTR  = 176;
    constexpr int B_PP  = KC * BSTR;
    constexpr int OFF_B = A_REG;
    constexpr int CHUNK = A_REG + 2*B_PP;      // 55296
    constexpr int AGRAN = 2 * 128 * (KC/8);
    constexpr int BGRAN = 2 * KC * 10;

    extern __shared__ __align__(128) char sm[];
    const uint32_t sb = smem_u32(sm);

    const int tid  = threadIdx.x;
    const int wid  = tid >> 5;
    const int lane = tid & 31;
    const int wm   = wid & 3;
    const int wn   = wid >> 2;
    const int la7  = lane & 7;
    const int hseg = lane >> 4;

    const int h  = blockIdx.x;
    const int w0 = blockIdx.y * 80;
    const int b  = blockIdx.z;
    const long rowpix = (long)b*HWHW + h*WW + w0;
    constexpr int NCH = KFIN / KC;

    float acc[10][4];
    #pragma unroll
    for (int i = 0; i < 10; i++)
        #pragma unroll
        for (int j = 0; j < 4; j++) acc[i][j] = 0.f;

    uint32_t laneA[2];
    #pragma unroll
    for (int mf = 0; mf < 2; mf++) {
        int row = wm*32 + mf*16 + (lane & 15);
        laneA[mf] = row * 128;
    }
    const int bg  = lane >> 3;
    const int bk4 = (bg & 1)*8 + la7;
    const int bn4 = (bg >> 1)*8;
    const int bk2 = ((lane >> 3) & 1)*8 + la7;

    auto stage = [&](int buf, int ch) {
        const int cc = ch * KC;
        const uint32_t sbuf = sb + buf*CHUNK;
        #pragma unroll 1
        for (int i = tid; i < AGRAN; i += 256) {
            int g  = i & 7;
            int m  = (i >> 3) & 127;
            int pr = i >> 10;
            uint32_t d = sbuf + pr*A_PP + m*128 + ((g ^ (m & 7)) << 4);
            const bf16* s = (pr ? wLo : wHi) + (long)m*KFIN + cc + g*8;
            CP16(d, s);
        }
        #pragma unroll 1
        for (int i = tid; i < BGRAN; i += 256) {
            int g  = i % 10;
            int t2 = i / 10;
            int pr = (t2 >= KC) ? 1 : 0;
            int rw = t2 - pr*KC;
            uint32_t d = sbuf + OFF_B + pr*B_PP + rw*BSTR + g*16;
            const bf16* s = (pr ? vLo : vHi) + (long)(cc + rw)*NPIX + rowpix + g*8;
            CP16(d, s);
        }
    };

    stage(0, 0);
    CPCOMMIT();

    int buf = 0;
    for (int ch = 0; ch < NCH; ch++) {
        if (ch + 1 < NCH) { stage(buf ^ 1, ch + 1); CPCOMMIT(); CPWAIT1(); }
        else              { CPWAIT0(); }
        __syncthreads();

        const uint32_t sbuf = sb + buf*CHUNK;
        #pragma unroll 1
        for (int ks = 0; ks < KC/16; ks++) {
            uint32_t ah[2][4], al[2][4], bh[5][2], bl[5][2];
            #pragma unroll
            for (int mf = 0; mf < 2; mf++) {
                uint32_t xo = (uint32_t)(((2*ks + hseg) ^ la7) << 4);
                ldsm4(ah[mf], sbuf + laneA[mf] + xo);
                ldsm4(al[mf], sbuf + A_PP + laneA[mf] + xo);
            }
            #pragma unroll
            for (int pr = 0; pr < 2; pr++) {
                uint32_t bbase = sbuf + OFF_B + pr*B_PP + (ks*16)*BSTR;
                uint32_t (*bf)[2] = pr ? bl : bh;
                ldsm4t(&bf[0][0], bbase + bk4*BSTR + (wn*40 + bn4)*2);
                ldsm4t(&bf[2][0], bbase + bk4*BSTR + (wn*40 + 16 + bn4)*2);
                ldsm2t(&bf[4][0], bbase + bk2*BSTR + (wn*40 + 32)*2);
            }
            #pragma unroll
            for (int n = 0; n < 5; n++)
                #pragma unroll
                for (int m = 0; m < 2; m++)
                    mma_bf16(acc[m*5+n], ah[m], bh[n]);
            #pragma unroll
            for (int n = 0; n < 5; n++)
                #pragma unroll
                for (int m = 0; m < 2; m++)
                    mma_bf16(acc[m*5+n], ah[m], bl[n]);
            #pragma unroll
            for (int n = 0; n < 5; n++)
                #pragma unroll
                for (int m = 0; m < 2; m++)
                    mma_bf16(acc[m*5+n], al[m], bh[n]);
        }
        __syncthreads();
        buf ^= 1;
    }

    #pragma unroll
    for (int m = 0; m < 2; m++) {
        #pragma unroll
        for (int half = 0; half < 2; half++) {
            int oc = wm*32 + m*16 + (lane >> 2) + half*8;
            float bz = bias[oc];
            #pragma unroll
            for (int n = 0; n < 5; n++) {
                int nn = wn*40 + n*8 + (lane & 3)*2;
                float2 o;
                o.x = acc[m*5+n][half*2+0] + bz;
                o.y = acc[m*5+n][half*2+1] + bz;
                *(float2*)(outF + ((long)(b*CC + oc)*HH + h)*WW + w0 + nn) = o;
            }
        }
    }
}

// ---------------- launcher ----------------
#define SMEM_GEMM (2*(2*16384 + 2*11264))       // 110592

extern "C" void kernel_launch(void* const* d_in, const int* in_sizes, int n_in,
                              void* d_out, int out_size)
{
    const float* x    = (const float*)d_in[0];
    const float* exf  = (const float*)d_in[1];
    const float* f1   = (const float*)d_in[2];
    const float* f2   = (const float*)d_in[3];
    const float* wgt  = (const float*)d_in[4];
    const float* bias = (const float*)d_in[5];
    const float* cw0  = (const float*)d_in[6];
    const float* cb0  = (const float*)d_in[7];
    const float* cw1  = (const float*)d_in[8];
    const float* cb1  = (const float*)d_in[9];
    const float* cw2  = (const float*)d_in[10];
    const float* cb2  = (const float*)d_in[11];
    const float* cw3  = (const float*)d_in[12];
    const float* cb3  = (const float*)d_in[13];
    float* out = (float*)d_out;

    cudaFuncSetAttribute(mma_conv_k<0>, cudaFuncAttributeMaxDynamicSharedMemorySize, SMEM_CONV);
    cudaFuncSetAttribute(mma_conv_k<1>, cudaFuncAttributeMaxDynamicSharedMemorySize, SMEM_CONV);
    cudaFuncSetAttribute(mma_gemm_k,    cudaFuncAttributeMaxDynamicSharedMemorySize, SMEM_GEMM);

    void *pefh, *pefl, *pAh, *pAl, *pBh, *pBl, *ph3, *pvh, *pvl;
    void *pw0h, *pw0l, *pw1h, *pw1l, *pw2h, *pw2l, *pw3h, *pw3l, *pwfh, *pwfl;
    cudaGetSymbolAddress(&pefh, g_ef_hi);  cudaGetSymbolAddress(&pefl, g_ef_lo);
    cudaGetSymbolAddress(&pAh, g_bA_hi);   cudaGetSymbolAddress(&pAl, g_bA_lo);
    cudaGetSymbolAddress(&pBh, g_bB_hi);   cudaGetSymbolAddress(&pBl, g_bB_lo);
    cudaGetSymbolAddress(&ph3, g_h3);
    cudaGetSymbolAddress(&pvh, g_val_hi);  cudaGetSymbolAddress(&pvl, g_val_lo);
    cudaGetSymbolAddress(&pw0h, g_w0_hi);  cudaGetSymbolAddress(&pw0l, g_w0_lo);
    cudaGetSymbolAddress(&pw1h, g_w1_hi);  cudaGetSymbolAddress(&pw1l, g_w1_lo);
    cudaGetSymbolAddress(&pw2h, g_w2_hi);  cudaGetSymbolAddress(&pw2l, g_w2_lo);
    cudaGetSymbolAddress(&pw3h, g_w3_hi);  cudaGetSymbolAddress(&pw3l, g_w3_lo);
    cudaGetSymbolAddress(&pwfh, g_wf_hi);  cudaGetSymbolAddress(&pwfl, g_wf_lo);

    zero_bufs_k<<<(BB*PH98*PW162*CC + 255)/256, 256>>>();
    pack_ef_k<<<(BB*PH98*PW162*CIN0P + 255)/256, 256>>>(exf, f1, f2);
    wprep_k<<<(9*CC*CIN0P + 255)/256, 256>>>(cw0, (bf16*)pw0h, (bf16*)pw0l, 128, 388, CIN0P, 128);

    dim3 g1(HH, 2, BB);
    mma_conv_k<0><<<g1, 256, SMEM_CONV>>>(
        (const bf16*)pw0h, (const bf16*)pw0l, (const bf16*)pefh, (const bf16*)pefl,
        cb0, nullptr, (bf16*)pAh, (bf16*)pAl, CIN0P, 1, 128);

    wprep_k<<<(9*CC*CC + 255)/256, 256>>>(cw1, (bf16*)pw1h, (bf16*)pw1l, 128, 128, 128, 128);

    mma_conv_k<0><<<g1, 256, SMEM_CONV>>>(
        (const bf16*)pw1h, (const bf16*)pw1l, (const bf16*)pAh, (const bf16*)pAl,
        cb1, nullptr, (bf16*)pBh, (bf16*)pBl, 128, 1, 128);

    wprep_k<<<(9*CC*CC + 255)/256, 256>>>(cw2, (bf16*)pw2h, (bf16*)pw2l, 128, 128, 128, 128);

    mma_conv_k<0><<<g1, 256, SMEM_CONV>>>(
        (const bf16*)pw2h, (const bf16*)pw2l, (const bf16*)pBh, (const bf16*)pBl,
        cb2, nullptr, (bf16*)pAh, (bf16*)pAl, 128, 1, 128);

    wprep_k<<<(9*512*CC + 255)/256, 256>>>(cw3, (bf16*)pw3h, (bf16*)pw3l, COFF, 128, 128, 512);

    dim3 g3(HH, 2, BB*4);
    mma_conv_k<1><<<g3, 256, SMEM_CONV>>>(
        (const bf16*)pw3h, (const bf16*)pw3l, (const bf16*)pAh, (const bf16*)pAl,
        cb3, (float*)ph3, nullptr, nullptr, 128, 4, COFF);

    wprep_fin_k<<<(CC*KFIN + 255)/256, 256>>>(wgt);

    gather_k<<<(BB*16*9*HWHW + 255)/256, 256>>>(x, f1, f2);

    dim3 gg(HH, 2, BB);
    mma_gemm_k<<<gg, 256, SMEM_GEMM>>>(
        (const bf16*)pwfh, (const bf16*)pwfl, (const bf16*)pvh, (const bf16*)pvl,
        bias, out);
}